// round 4
// baseline (speedup 1.0000x reference)
#include <cuda_runtime.h>
#include <math.h>

#define NN 8192
#define TPB 256
#define JCH 16                 // j chunks for the pair kernel
#define JTILE (NN / JCH)       // 512 j per tile
#define IBLK (NN / TPB)        // 32 i-blocks

// ---------------- device scratch (no allocations allowed) ----------------
__device__ float  g_wm[NN];    // weights * (label==0)
__device__ float  g_Ra[NN];    // row sums: sum_j wm_j |x_i - x_j|
__device__ float  g_Rb[NN];    // row sums: sum_j wm_j |y_i - y_j|
__device__ double g_red[8];    // 0:bce_sum 1:nf 2:sw 3:swx 4:swx2 5:swy 6:swy2
__device__ double g_tab;       // T_ab = sum_ij wm_i wm_j |dx||dy|

// ---------------- helpers ----------------
__device__ __forceinline__ double block_reduce_d(double v, double* sbuf) {
    int t = threadIdx.x;
    sbuf[t] = v;
    __syncthreads();
    for (int s = blockDim.x >> 1; s > 0; s >>= 1) {
        if (t < s) sbuf[t] += sbuf[t + s];
        __syncthreads();
    }
    double r = sbuf[0];
    __syncthreads();
    return r;
}

// ---------------- kernel 0: zero the scalar accumulators ----------------
__global__ void k_zero() {
    int t = threadIdx.x;
    if (t < 8) g_red[t] = 0.0;
    if (t == 8) g_tab = 0.0;
}

// ---------------- kernel 1: wm, zero row sums, O(N) reductions ----------------
__global__ void k_prep(const float* __restrict__ x, const int* __restrict__ lbl,
                       const float* __restrict__ y, const float* __restrict__ w) {
    __shared__ double sbuf[TPB];
    int i = blockIdx.x * TPB + threadIdx.x;

    float xi = x[i];
    float yi = y[i];
    float wi = w[i];
    int   li = lbl[i];

    float m  = (li == 0) ? 1.0f : 0.0f;
    float wm = wi * m;
    g_wm[i] = wm;
    g_Ra[i] = 0.0f;
    g_Rb[i] = 0.0f;

    // BCE term (torch F.binary_cross_entropy with clamp at -100, weighted)
    float yf     = (float)li;
    float logp   = fmaxf(logf(xi), -100.0f);
    float log1mp = fmaxf(log1pf(-xi), -100.0f);
    float bce    = wi * (-(yf * logp + (1.0f - yf) * log1mp));

    double vals[7];
    vals[0] = (double)bce;
    vals[1] = (double)m;                       // nf
    vals[2] = (double)wm;                      // sw
    vals[3] = (double)wm * xi;                 // swx
    vals[4] = (double)wm * xi * xi;            // swx2
    vals[5] = (double)wm * yi;                 // swy
    vals[6] = (double)wm * yi * yi;            // swy2

    #pragma unroll
    for (int k = 0; k < 7; k++) {
        double r = block_reduce_d(vals[k], sbuf);
        if (threadIdx.x == 0) atomicAdd(&g_red[k], r);
    }
}

// ---------------- kernel 2: the O(N^2) fused pass ----------------
// Computes Ra_i, Rb_i and T_ab in a single sweep over all pairs.
// grid = (IBLK, JCH), block = TPB. Thread owns one i, loops over a j tile.
// Shared tile packed as float4 (x, y, wm, pad) -> one LDS.128 per j.
__global__ void __launch_bounds__(TPB) k_pairs(const float* __restrict__ x,
                                               const float* __restrict__ y) {
    __shared__ float4 s4[JTILE];
    __shared__ double sred[TPB];

    int tid = threadIdx.x;
    int i   = blockIdx.x * TPB + tid;
    int j0  = blockIdx.y * JTILE;

    for (int k = tid; k < JTILE; k += TPB) {
        float4 v;
        v.x = x[j0 + k];
        v.y = y[j0 + k];
        v.z = g_wm[j0 + k];
        v.w = 0.0f;
        s4[k] = v;
    }
    __syncthreads();

    float xi = x[i];
    float yi = y[i];

    float ra0 = 0.f, ra1 = 0.f;
    float rb0 = 0.f, rb1 = 0.f;
    float t0  = 0.f, t1  = 0.f;

    #pragma unroll 4
    for (int k = 0; k < JTILE; k += 2) {
        {
            float4 v = s4[k];
            float a  = fabsf(xi - v.x);
            float b  = fabsf(yi - v.y);
            float u  = v.z * a;
            ra0 += u;
            rb0  = fmaf(v.z, b, rb0);
            t0   = fmaf(u, b, t0);
        }
        {
            float4 v = s4[k + 1];
            float a  = fabsf(xi - v.x);
            float b  = fabsf(yi - v.y);
            float u  = v.z * a;
            ra1 += u;
            rb1  = fmaf(v.z, b, rb1);
            t1   = fmaf(u, b, t1);
        }
    }

    atomicAdd(&g_Ra[i], ra0 + ra1);
    atomicAdd(&g_Rb[i], rb0 + rb1);

    // weight the T_ab partial by wm_i, reduce block-wide in double
    float tabw = g_wm[i] * (t0 + t1);
    double r = block_reduce_d((double)tabw, sred);
    if (tid == 0) atomicAdd(&g_tab, r);
}

// ---------------- kernel 3: final O(N) reductions + combine ----------------
__global__ void k_final(float* __restrict__ out) {
    __shared__ double sbuf[1024];
    int tid = threadIdx.x;

    double uab = 0.0, uaa = 0.0, ubb = 0.0, va = 0.0, vb = 0.0;
    for (int i = tid; i < NN; i += 1024) {
        double wm = (double)g_wm[i];
        double Ra = (double)g_Ra[i];
        double Rb = (double)g_Rb[i];
        va  += wm * Ra;
        vb  += wm * Rb;
        uab += wm * Ra * Rb;
        uaa += wm * Ra * Ra;
        ubb += wm * Rb * Rb;
    }

    uab = block_reduce_d(uab, sbuf);
    uaa = block_reduce_d(uaa, sbuf);
    ubb = block_reduce_d(ubb, sbuf);
    va  = block_reduce_d(va,  sbuf);
    vb  = block_reduce_d(vb,  sbuf);

    if (tid == 0) {
        double bce_sum = g_red[0];
        double nf      = g_red[1];
        double sw      = g_red[2];
        double swx     = g_red[3];
        double swx2    = g_red[4];
        double swy     = g_red[5];
        double swy2    = g_red[6];
        double Tab     = g_tab;

        // closed forms for sum_ij wm_i wm_j (dx)^2 and (dy)^2
        double Taa = 2.0 * (sw * swx2 - swx * swx);
        double Tbb = 2.0 * (sw * swy2 - swy * swy);

        // Full weighted double-centering expansion (sw != nf!):
        //   <A.B> = Tab - (4/nf - 2*sw/nf^2) * uab + c * va*vb
        //   c     = (4 - 4*sw/nf + (sw/nf)^2) / nf^2
        double inv_nf = 1.0 / nf;
        double r      = sw * inv_nf;
        double coef_u = (4.0 - 2.0 * r) * inv_nf;
        double c      = (4.0 - 4.0 * r + r * r) * inv_nf * inv_nf;

        double Eab = Tab - coef_u * uab + c * va * vb;
        double Eaa = Taa - coef_u * uaa + c * va * va;
        double Ebb = Tbb - coef_u * ubb + c * vb * vb;

        // the /nf^2 normalizations of AB, AA, BB cancel in the ratio
        double dcorr = (Eab * Eab) / (Eaa * Ebb);   // DCORR_POWER == 2
        double bce   = bce_sum / (double)NN;
        double disco = 0.1 * dcorr;                 // DISCO_LAMBDA

        out[0] = (float)(bce + disco);
        out[1] = (float)bce;
        out[2] = (float)disco;
    }
}

// ---------------- launch ----------------
extern "C" void kernel_launch(void* const* d_in, const int* in_sizes, int n_in,
                              void* d_out, int out_size) {
    const float* inferences   = (const float*)d_in[0];
    const int*   labels       = (const int*)d_in[1];
    const float* disco_target = (const float*)d_in[2];
    const float* weights      = (const float*)d_in[3];
    float* out = (float*)d_out;

    k_zero<<<1, 32>>>();
    k_prep<<<IBLK, TPB>>>(inferences, labels, disco_target, weights);
    k_pairs<<<dim3(IBLK, JCH), TPB>>>(inferences, disco_target);
    k_final<<<1, 1024>>>(out);
}

// round 5
// speedup vs baseline: 2.2583x; 2.2583x over previous
#include <cuda_runtime.h>
#include <math.h>

#define NN 8192
#define TPB 256
#define JCH 64                  // j chunks for the pair kernel
#define JTILE (NN / JCH)        // 128 j per tile
#define JT2 (JTILE / 2)         // 64 packed j-pairs per tile
#define IBLK2 (NN / (2 * TPB))  // 16 i-blocks (each thread owns 2 i's)
#define IBLK (NN / TPB)         // 32 blocks for O(N) kernels

// ---------------- device scratch (no allocations allowed) ----------------
__device__ float  g_wm[NN];     // weights * (label==0)
__device__ float  g_Ra[NN];     // row sums: sum_j wm_j |x_i - x_j|
__device__ float  g_Rb[NN];     // row sums: sum_j wm_j |y_i - y_j|
__device__ double g_red[8];     // 0:bce_sum 1:nf 2:sw 3:swx 4:swx2 5:swy 6:swy2
__device__ double g_red2[8];    // 0:va 1:vb 2:uab 3:uaa 4:ubb
__device__ double g_tab;        // T_ab = sum_ij wm_i wm_j |dx||dy|

// ---------------- packed f32x2 helpers (sm_103a FFMA2 path) ----------------
typedef unsigned long long u64;
#define ABS2 0x7FFFFFFF7FFFFFFFULL

__device__ __forceinline__ u64 f2pack(float a, float b) {
    u64 r; asm("mov.b64 %0, {%1, %2};" : "=l"(r) : "f"(a), "f"(b)); return r;
}
__device__ __forceinline__ void f2unpack(u64 v, float& a, float& b) {
    asm("mov.b64 {%0, %1}, %2;" : "=f"(a), "=f"(b) : "l"(v));
}
__device__ __forceinline__ u64 addx2(u64 a, u64 b) {
    u64 r; asm("add.rn.f32x2 %0, %1, %2;" : "=l"(r) : "l"(a), "l"(b)); return r;
}
__device__ __forceinline__ u64 mulx2(u64 a, u64 b) {
    u64 r; asm("mul.rn.f32x2 %0, %1, %2;" : "=l"(r) : "l"(a), "l"(b)); return r;
}
__device__ __forceinline__ u64 fmax2(u64 a, u64 b, u64 c) {
    u64 r; asm("fma.rn.f32x2 %0, %1, %2, %3;" : "=l"(r) : "l"(a), "l"(b), "l"(c)); return r;
}

// ---------------- kernel 0: zero the scalar accumulators ----------------
__global__ void k_zero() {
    int t = threadIdx.x;
    if (t < 8)  g_red[t]  = 0.0;
    if (t >= 8 && t < 16) g_red2[t - 8] = 0.0;
    if (t == 16) g_tab = 0.0;
}

// ---------------- kernel 1: wm, zero row sums, O(N) reductions ----------------
__global__ void k_prep(const float* __restrict__ x, const int* __restrict__ lbl,
                       const float* __restrict__ y, const float* __restrict__ w) {
    __shared__ double sred[8][7];
    int tid = threadIdx.x;
    int i = blockIdx.x * TPB + tid;
    int lane = tid & 31, wid = tid >> 5;

    float xi = x[i];
    float yi = y[i];
    float wi = w[i];
    int   li = lbl[i];

    float m  = (li == 0) ? 1.0f : 0.0f;
    float wm = wi * m;
    g_wm[i] = wm;
    g_Ra[i] = 0.0f;
    g_Rb[i] = 0.0f;

    // BCE term (torch F.binary_cross_entropy with clamp at -100, weighted)
    float yf     = (float)li;
    float logp   = fmaxf(logf(xi), -100.0f);
    float log1mp = fmaxf(log1pf(-xi), -100.0f);
    float bce    = wi * (-(yf * logp + (1.0f - yf) * log1mp));

    double vals[7];
    vals[0] = (double)bce;
    vals[1] = (double)m;                       // nf
    vals[2] = (double)wm;                      // sw
    vals[3] = (double)wm * xi;                 // swx
    vals[4] = (double)wm * xi * xi;            // swx2
    vals[5] = (double)wm * yi;                 // swy
    vals[6] = (double)wm * yi * yi;            // swy2

    // warp shuffle reduce all 7, then cross-warp via shared
    #pragma unroll
    for (int k = 0; k < 7; k++) {
        double v = vals[k];
        #pragma unroll
        for (int s = 16; s > 0; s >>= 1)
            v += __shfl_down_sync(0xFFFFFFFFu, v, s);
        if (lane == 0) sred[wid][k] = v;
    }
    __syncthreads();
    if (wid == 0 && lane < 7) {
        double s = 0.0;
        #pragma unroll
        for (int ww = 0; ww < 8; ww++) s += sred[ww][lane];
        atomicAdd(&g_red[lane], s);
    }
}

// ---------------- kernel 2: the O(N^2) fused pass (packed f32x2) ----------------
// Thread owns i0 and i1 = i0 + NN/2; processes 2 j's per packed op.
// Shared tile holds NEGATED x/y pairs so subtraction becomes add.rn.f32x2.
__global__ void __launch_bounds__(TPB) k_pairs(const float* __restrict__ x,
                                               const float* __restrict__ y) {
    __shared__ ulonglong2 sxy[JT2];   // {(-x_{2k},-x_{2k+1}), (-y_{2k},-y_{2k+1})}
    __shared__ u64 sw2[JT2];          // (wm_{2k}, wm_{2k+1})
    __shared__ double sred[TPB / 32];

    int tid = threadIdx.x;
    int i0  = blockIdx.x * TPB + tid;
    int i1  = i0 + NN / 2;
    int j0  = blockIdx.y * JTILE;
    int lane = tid & 31, wid = tid >> 5;

    if (tid < JT2) {
        int j = j0 + 2 * tid;
        ulonglong2 v;
        v.x = f2pack(-x[j], -x[j + 1]);
        v.y = f2pack(-y[j], -y[j + 1]);
        sxy[tid] = v;
        sw2[tid] = f2pack(g_wm[j], g_wm[j + 1]);
    }
    __syncthreads();

    float xi0f = x[i0], xi1f = x[i1];
    float yi0f = y[i0], yi1f = y[i1];
    u64 xi0 = f2pack(xi0f, xi0f);
    u64 xi1 = f2pack(xi1f, xi1f);
    u64 yi0 = f2pack(yi0f, yi0f);
    u64 yi1 = f2pack(yi1f, yi1f);

    u64 ra0 = 0ull, rb0 = 0ull, t0 = 0ull;
    u64 ra1 = 0ull, rb1 = 0ull, t1 = 0ull;

    #pragma unroll 4
    for (int k = 0; k < JT2; k++) {
        ulonglong2 v = sxy[k];
        u64 w2 = sw2[k];

        u64 aa0 = addx2(xi0, v.x) & ABS2;   // |x_i0 - x_j| x2
        u64 ab0 = addx2(yi0, v.y) & ABS2;
        u64 u0  = mulx2(w2, aa0);
        ra0 = addx2(ra0, u0);
        rb0 = fmax2(w2, ab0, rb0);
        t0  = fmax2(u0, ab0, t0);

        u64 aa1 = addx2(xi1, v.x) & ABS2;
        u64 ab1 = addx2(yi1, v.y) & ABS2;
        u64 u1  = mulx2(w2, aa1);
        ra1 = addx2(ra1, u1);
        rb1 = fmax2(w2, ab1, rb1);
        t1  = fmax2(u1, ab1, t1);
    }

    float lo, hi;
    f2unpack(ra0, lo, hi); float raf0 = lo + hi;
    f2unpack(rb0, lo, hi); float rbf0 = lo + hi;
    f2unpack(t0,  lo, hi); float tf0  = lo + hi;
    f2unpack(ra1, lo, hi); float raf1 = lo + hi;
    f2unpack(rb1, lo, hi); float rbf1 = lo + hi;
    f2unpack(t1,  lo, hi); float tf1  = lo + hi;

    atomicAdd(&g_Ra[i0], raf0);
    atomicAdd(&g_Rb[i0], rbf0);
    atomicAdd(&g_Ra[i1], raf1);
    atomicAdd(&g_Rb[i1], rbf1);

    // T_ab partial, weighted by wm_i, block-reduced in double
    double tp = (double)(g_wm[i0] * tf0) + (double)(g_wm[i1] * tf1);
    #pragma unroll
    for (int s = 16; s > 0; s >>= 1)
        tp += __shfl_down_sync(0xFFFFFFFFu, tp, s);
    if (lane == 0) sred[wid] = tp;
    __syncthreads();
    if (tid == 0) {
        double s = 0.0;
        #pragma unroll
        for (int ww = 0; ww < TPB / 32; ww++) s += sred[ww];
        atomicAdd(&g_tab, s);
    }
}

// ---------------- kernel 3: parallel O(N) epilogue reductions ----------------
__global__ void k_post() {
    __shared__ double sred[8][5];
    int tid = threadIdx.x;
    int i = blockIdx.x * TPB + tid;
    int lane = tid & 31, wid = tid >> 5;

    double wm = (double)g_wm[i];
    double Ra = (double)g_Ra[i];
    double Rb = (double)g_Rb[i];

    double vals[5];
    vals[0] = wm * Ra;            // va
    vals[1] = wm * Rb;            // vb
    vals[2] = wm * Ra * Rb;       // uab
    vals[3] = wm * Ra * Ra;       // uaa
    vals[4] = wm * Rb * Rb;       // ubb

    #pragma unroll
    for (int k = 0; k < 5; k++) {
        double v = vals[k];
        #pragma unroll
        for (int s = 16; s > 0; s >>= 1)
            v += __shfl_down_sync(0xFFFFFFFFu, v, s);
        if (lane == 0) sred[wid][k] = v;
    }
    __syncthreads();
    if (wid == 0 && lane < 5) {
        double s = 0.0;
        #pragma unroll
        for (int ww = 0; ww < 8; ww++) s += sred[ww][lane];
        atomicAdd(&g_red2[lane], s);
    }
}

// ---------------- kernel 4: final scalar combine ----------------
__global__ void k_combine(float* __restrict__ out) {
    double bce_sum = g_red[0];
    double nf      = g_red[1];
    double sw      = g_red[2];
    double swx     = g_red[3];
    double swx2    = g_red[4];
    double swy     = g_red[5];
    double swy2    = g_red[6];
    double va      = g_red2[0];
    double vb      = g_red2[1];
    double uab     = g_red2[2];
    double uaa     = g_red2[3];
    double ubb     = g_red2[4];
    double Tab     = g_tab;

    // closed forms for sum_ij wm_i wm_j (dx)^2 and (dy)^2
    double Taa = 2.0 * (sw * swx2 - swx * swx);
    double Tbb = 2.0 * (sw * swy2 - swy * swy);

    // Full weighted double-centering expansion (sw != nf!):
    //   <A.B> = Tab - (4/nf - 2*sw/nf^2) * uab + c * va*vb
    //   c     = (4 - 4*sw/nf + (sw/nf)^2) / nf^2
    double inv_nf = 1.0 / nf;
    double r      = sw * inv_nf;
    double coef_u = (4.0 - 2.0 * r) * inv_nf;
    double c      = (4.0 - 4.0 * r + r * r) * inv_nf * inv_nf;

    double Eab = Tab - coef_u * uab + c * va * vb;
    double Eaa = Taa - coef_u * uaa + c * va * va;
    double Ebb = Tbb - coef_u * ubb + c * vb * vb;

    // the /nf^2 normalizations of AB, AA, BB cancel in the ratio
    double dcorr = (Eab * Eab) / (Eaa * Ebb);   // DCORR_POWER == 2
    double bce   = bce_sum / (double)NN;
    double disco = 0.1 * dcorr;                 // DISCO_LAMBDA

    out[0] = (float)(bce + disco);
    out[1] = (float)bce;
    out[2] = (float)disco;
}

// ---------------- launch ----------------
extern "C" void kernel_launch(void* const* d_in, const int* in_sizes, int n_in,
                              void* d_out, int out_size) {
    const float* inferences   = (const float*)d_in[0];
    const int*   labels       = (const int*)d_in[1];
    const float* disco_target = (const float*)d_in[2];
    const float* weights      = (const float*)d_in[3];
    float* out = (float*)d_out;

    k_zero<<<1, 32>>>();
    k_prep<<<IBLK, TPB>>>(inferences, labels, disco_target, weights);
    k_pairs<<<dim3(IBLK2, JCH), TPB>>>(inferences, disco_target);
    k_post<<<IBLK, TPB>>>();
    k_combine<<<1, 1>>>(out);
}